// round 9
// baseline (speedup 1.0000x reference)
#include <cuda_runtime.h>
#include <math.h>

#define Bb      128
#define Ll      2048
#define NOBS    32
#define NHID    512
#define NSTEPS  (Ll - 1)          // 2047
#define NCTA    128
#define NTHREADS 128
#define NBARS   (NSTEPS - 1)
typedef unsigned long long u64;
#define GRP_CTAS 16               // CTAs per m-tile group
#define BARMOD  ((u64)NBARS * GRP_CTAS)

// SMEM: A interleaved [256 k2][16 cp][4 floats] + X pair-major [8][514] u64
#define SA2_FLOATS (256 * 16 * 4)               // 16384 floats = 65536 B
#define SX_STRIDE  514                          // u64 rows (4112 B, 16B-aligned)
#define SX_U64     (8 * SX_STRIDE)
#define SMEM_BYTES (SA2_FLOATS * 4 + SX_U64 * 8)  // 98432 B

// per-m-tile-group barrier counters, one 128B line each
__device__ u64 g_counts[8][16];

// ---------------------------------------------------------------------------
__device__ __forceinline__ u64 pack2(float a, float b) {
    u64 r;
    asm("mov.b64 %0, {%1, %2};" : "=l"(r) : "f"(a), "f"(b));
    return r;
}
__device__ __forceinline__ void unpack2(u64 v, float& a, float& b) {
    asm("mov.b64 {%0, %1}, %2;" : "=f"(a), "=f"(b) : "l"(v));
}
__device__ __forceinline__ void ffma2(u64& acc, u64 a, u64 x) {
    asm("fma.rn.f32x2 %0, %1, %2, %0;" : "+l"(acc) : "l"(a), "l"(x));
}

// XLA EmitFastTanh (fma path) — verified bit-exact (rel_err 0.0). DO NOT CHANGE.
__device__ __forceinline__ float tanh_xla(float x) {
    const float kClamp = 7.99881172180175781f;
    float xc = fminf(fmaxf(x, -kClamp), kClamp);
    float x2 = __fmul_rn(xc, xc);
    float num = -2.76076847742355e-16f;
    num = fmaf(x2, num, 2.00018790482477e-13f);
    num = fmaf(x2, num, -8.60467152213735e-11f);
    num = fmaf(x2, num, 5.12229709037114e-08f);
    num = fmaf(x2, num, 1.48572235717979e-05f);
    num = fmaf(x2, num, 6.37261928875436e-04f);
    num = fmaf(x2, num, 4.89352455891786e-03f);
    num = __fmul_rn(xc, num);
    float den = 1.19825839466702e-06f;
    den = fmaf(x2, den, 1.18534705686654e-04f);
    den = fmaf(x2, den, 2.26843463243900e-03f);
    den = fmaf(x2, den, 4.89352518554385e-03f);
    float r = __fdiv_rn(num, den);
    return (fabsf(x) < 0.0004f) ? x : r;
}

// group barrier: release-arrive + acquire-poll on the group's counter
__device__ __forceinline__ void group_barrier(u64* ctr, u64 target) {
    __syncthreads();
    if (threadIdx.x == 0) {
        asm volatile("red.global.release.gpu.add.u64 [%0], %1;"
                     :: "l"(ctr), "n"(1ULL) : "memory");
        u64 v;
        do {
            asm volatile("ld.global.acquire.gpu.u64 %0, [%1];"
                         : "=l"(v) : "l"(ctr));
        } while (v < target);
    }
    __syncthreads();
}

// 8-k2 block compute, bit-exact ascending-k chain order
#define FMA_BLOCK(Xb_, Ab_)                                          \
    _Pragma("unroll")                                                \
    for (int j = 0; j < 8; j++) {                                    \
        ffma2(acc0, pack2(Ab_[j].x, Ab_[j].x), Xb_[j].x);            \
        ffma2(acc1, pack2(Ab_[j].z, Ab_[j].z), Xb_[j].x);            \
        ffma2(acc0, pack2(Ab_[j].y, Ab_[j].y), Xb_[j].y);            \
        ffma2(acc1, pack2(Ab_[j].w, Ab_[j].w), Xb_[j].y);            \
    }

#define LOAD_BLOCK(Xb_, Ab_, base_)                                  \
    _Pragma("unroll")                                                \
    for (int j = 0; j < 8; j++) {                                    \
        Xb_[j] = *(const ulonglong2*)(xr + 2 * ((base_) + j));       \
        Ab_[j] = aF[((base_) + j) * 16];                             \
    }

// ---------------------------------------------------------------------------
// Persistent HCNN scan, order-exact fp32.
// 128 CTAs = 16 n-tiles (32 cols) x 8 m-tile GROUPS (16 batches = 8 pairs).
// Per-group (16-CTA) barriers. 128 threads = 4 warps, all compute:
// thread tile = 1 pair x 2 cols; inner loop explicitly double-buffered
// (8-k2 register blocks) so LDS latency is fully covered.
// ---------------------------------------------------------------------------
__global__ void __launch_bounds__(NTHREADS, 1) ptf_persistent(
    const float* __restrict__ data,   // [B, L, NOBS]
    const float* __restrict__ Amat,   // [NHID, NHID]
    const float* __restrict__ h0,     // [NHID]
    float* __restrict__ exps,
    float* __restrict__ states,       // doubles as the recurrent state
    float* __restrict__ deltas,
    float* __restrict__ partials)
{
    extern __shared__ char smem_raw[];
    float* sA2 = (float*)smem_raw;                        // [256][16][4]
    u64*   sx  = (u64*)(smem_raw + SA2_FLOATS * 4);       // [8][514]

    const int tid = threadIdx.x;
    const int w   = tid >> 5;                 // warp 0..3
    const int l   = tid & 31;
    const int nt  = blockIdx.x & 15;
    const int mt  = blockIdx.x >> 4;
    const int n0  = nt * 32;
    const int m0  = mt * 16;
    u64* ctr = &g_counts[mt][0];

    // ---- barrier base (monotonic counter across graph replays) ----
    u64 base;
    {
        u64 v;
        asm volatile("ld.global.acquire.gpu.u64 %0, [%1];" : "=l"(v) : "l"(ctr));
        base = v - (v % BARMOD);
    }

    // ---- one-time: A -> sA2[k2][cp][4] = {a_n[2k2], a_n[2k2+1],
    //                                       a_n1[2k2], a_n1[2k2+1]} ----
    for (int i = tid; i < 256 * 16; i += NTHREADS) {
        const int k2 = i >> 4;           // 0..255
        const int cp = i & 15;           // 0..15
        const int n  = n0 + 2 * cp;
        float2 a0 = *(const float2*)&Amat[(size_t)n * NHID + 2 * k2];
        float2 a1 = *(const float2*)&Amat[(size_t)(n + 1) * NHID + 2 * k2];
        float4 v  = make_float4(a0.x, a0.y, a1.x, a1.y);
        *(float4*)&sA2[(size_t)i * 4] = v;
    }
    __syncthreads();

    // compute-thread identifiers
    const int p   = tid & 7;                  // pair 0..7
    const int cp  = tid >> 3;                 // col-pair 0..15
    const int nA  = n0 + 2 * cp;              // cols nA, nA+1
    const int bA  = m0 + p;                   // batches bA, bA+8
    const int bB  = bA + 8;
    const u64*    xr = sx + (size_t)p * SX_STRIDE;
    const float4* aF = (const float4*)sA2 + cp;     // + k2*16

    for (int t = 0; t < NSTEPS; t++) {
        // ---------------- stage state pairs (+ exact injection + outputs) ----
        // warp w stages pairs w and w+4; 4 float4-chunks per pair per thread
        #pragma unroll
        for (int r = 0; r < 2; r++) {
            const int sp  = w + 4 * r;
            const int sbA = m0 + sp;
            const int sbB = sbA + 8;
            #pragma unroll
            for (int j = 0; j < 4; j++) {
                const int k0 = 4 * l + 128 * j;
                const float* srcA = (t == 0) ? (h0 + k0)
                                  : (states + ((size_t)sbA * Ll + t) * NHID + k0);
                const float* srcB = (t == 0) ? (h0 + k0)
                                  : (states + ((size_t)sbB * Ll + t) * NHID + k0);
                float4 a4 = *(const float4*)srcA;
                float4 b4 = *(const float4*)srcB;

                if (t == 0 && nt == 0) {      // states[:,0,:] = s0 (pre-inject)
                    *(float4*)&states[((size_t)sbA * Ll) * NHID + k0] = a4;
                    *(float4*)&states[((size_t)sbB * Ll) * NHID + k0] = b4;
                }
                if (k0 < NOBS) {              // teacher forcing: s + (y - s)
                    float4 yA = *(const float4*)&data[((size_t)sbA * Ll + t) * NOBS + k0];
                    float4 yB = *(const float4*)&data[((size_t)sbB * Ll + t) * NOBS + k0];
                    float4 dA, dB;
                    dA.x = __fsub_rn(yA.x, a4.x); dA.y = __fsub_rn(yA.y, a4.y);
                    dA.z = __fsub_rn(yA.z, a4.z); dA.w = __fsub_rn(yA.w, a4.w);
                    dB.x = __fsub_rn(yB.x, b4.x); dB.y = __fsub_rn(yB.y, b4.y);
                    dB.z = __fsub_rn(yB.z, b4.z); dB.w = __fsub_rn(yB.w, b4.w);
                    if (nt == 0) {
                        size_t oA = ((size_t)sbA * Ll + t) * NOBS + k0;
                        size_t oB = ((size_t)sbB * Ll + t) * NOBS + k0;
                        *(float4*)&exps[oA] = a4;  *(float4*)&exps[oB] = b4;
                        *(float4*)&deltas[oA]   = dA; *(float4*)&deltas[oB]   = dB;
                        *(float4*)&partials[oA] = dA; *(float4*)&partials[oB] = dB;
                    }
                    a4.x = __fadd_rn(a4.x, dA.x); a4.y = __fadd_rn(a4.y, dA.y);
                    a4.z = __fadd_rn(a4.z, dA.z); a4.w = __fadd_rn(a4.w, dA.w);
                    b4.x = __fadd_rn(b4.x, dB.x); b4.y = __fadd_rn(b4.y, dB.y);
                    b4.z = __fadd_rn(b4.z, dB.z); b4.w = __fadd_rn(b4.w, dB.w);
                }
                u64* dst = &sx[(size_t)sp * SX_STRIDE + k0];
                ulonglong2 lo, hi;
                lo.x = pack2(a4.x, b4.x); lo.y = pack2(a4.y, b4.y);
                hi.x = pack2(a4.z, b4.z); hi.y = pack2(a4.w, b4.w);
                *(ulonglong2*)(dst)     = lo;
                *(ulonglong2*)(dst + 2) = hi;
            }
        }
        __syncthreads();

        // -------- compute: double-buffered 8-k2 blocks, ascending-k chains ---
        u64 acc0 = 0, acc1 = 0;               // cols nA, nA+1 (both lanes 0.0f)
        {
            ulonglong2 Xa[8], Xb[8];
            float4 Aa[8], Ab[8];
            LOAD_BLOCK(Xa, Aa, 0)             // block 0

            #pragma unroll 1
            for (int blk = 0; blk < 30; blk += 2) {
                LOAD_BLOCK(Xb, Ab, (blk + 1) * 8)   // prefetch odd block
                FMA_BLOCK(Xa, Aa)                    // compute even block
                LOAD_BLOCK(Xa, Aa, (blk + 2) * 8)   // prefetch next even
                FMA_BLOCK(Xb, Ab)                    // compute odd block
            }
            // tail: Xa holds block 30
            LOAD_BLOCK(Xb, Ab, 31 * 8)
            FMA_BLOCK(Xa, Aa)
            FMA_BLOCK(Xb, Ab)
        }

        float z0a, z0b, z1a, z1b;
        unpack2(acc0, z0a, z0b);              // (bA,nA), (bB,nA)
        unpack2(acc1, z1a, z1b);              // (bA,nA+1), (bB,nA+1)
        const float h00 = tanh_xla(z0a);
        const float h10 = tanh_xla(z1a);
        const float h01 = tanh_xla(z0b);
        const float h11 = tanh_xla(z1b);

        // states writes: per batch, cols (nA, nA+1) adjacent -> STG.64
        float* so = states + ((size_t)t + 1) * NHID + nA;
        *(float2*)(so + (size_t)bA * Ll * NHID) = make_float2(h00, h10);
        *(float2*)(so + (size_t)bB * Ll * NHID) = make_float2(h01, h11);

        if (t == NSTEPS - 1 && nt == 0) {     // nA, nA+1 < 32 here
            size_t oA = ((size_t)bA * Ll + (Ll - 1)) * NOBS + nA;
            size_t oB = ((size_t)bB * Ll + (Ll - 1)) * NOBS + nA;
            size_t dIA = ((size_t)bA * Ll + (Ll - 2)) * NOBS + nA;
            size_t dIB = ((size_t)bB * Ll + (Ll - 2)) * NOBS + nA;
            exps[oA] = h00; exps[oA + 1] = h10;
            exps[oB] = h01; exps[oB + 1] = h11;
            float dAx = __fsub_rn(data[dIA],     h00);
            float dAy = __fsub_rn(data[dIA + 1], h10);
            float dBx = __fsub_rn(data[dIB],     h01);
            float dBy = __fsub_rn(data[dIB + 1], h11);
            deltas[oA] = dAx; deltas[oA + 1] = dAy;
            deltas[oB] = dBx; deltas[oB + 1] = dBy;
            partials[oA] = dAx; partials[oA + 1] = dAy;
            partials[oB] = dBx; partials[oB + 1] = dBy;
        }

        if (t < NSTEPS - 1)
            group_barrier(ctr, base + (u64)(t + 1) * GRP_CTAS);
    }
}

// ---------------------------------------------------------------------------
extern "C" void kernel_launch(void* const* d_in, const int* in_sizes, int n_in,
                              void* d_out, int out_size) {
    const float* data = (const float*)d_in[0];  // [128,2048,32]
    const float* A    = (const float*)d_in[1];  // [512,512]
    const float* h0   = (const float*)d_in[2];  // [1,512]
    // d_in[3] = prob (0) -> dropout identity

    float* out      = (float*)d_out;
    float* exps     = out;
    float* states   = exps   + (size_t)Bb * Ll * NOBS;
    float* deltas   = states + (size_t)Bb * Ll * NHID;
    float* partials = deltas + (size_t)Bb * Ll * NOBS;

    cudaFuncSetAttribute(ptf_persistent,
                         cudaFuncAttributeMaxDynamicSharedMemorySize, SMEM_BYTES);
    ptf_persistent<<<NCTA, NTHREADS, SMEM_BYTES>>>(data, A, h0,
                                                   exps, states, deltas, partials);
}